// round 12
// baseline (speedup 1.0000x reference)
#include <cuda_runtime.h>
#include <cuda_fp16.h>
#include <mma.h>
#include <cstddef>
#include <cstdint>

using namespace nvcuda;

#define D_MODEL 1024
#define SEQ     2048
#define BATCH   4
#define HEADS   16
#define HDIM    64
#define MROWS   (BATCH * SEQ)   /* 8192 */

// Scratch (alloc-free rule: __device__ globals)
__device__ __half g_qh[MROWS * D_MODEL];
__device__ __half g_kh[MROWS * D_MODEL];
__device__ __half g_vh[MROWS * D_MODEL];
__device__ __half g_xh[MROWS * D_MODEL];
__device__ __half g_oh[MROWS * D_MODEL];
__device__ __half g_wth[4 * D_MODEL * D_MODEL];   // transposed half weights (q,k,v,o)

// ---------------------------------------------------------------------------
// helpers
// ---------------------------------------------------------------------------
__device__ __forceinline__ uint32_t smem_u32(const void* p) {
    uint32_t a;
    asm("{ .reg .u64 t; cvta.to.shared.u64 t, %1; cvt.u32.u64 %0, t; }"
        : "=r"(a) : "l"(p));
    return a;
}
__device__ __forceinline__ void cp_async16(uint32_t dst, const void* src) {
    asm volatile("cp.async.cg.shared.global [%0], [%1], 16;"
                 :: "r"(dst), "l"(__cvta_generic_to_global(src)) : "memory");
}
__device__ __forceinline__ void cp_commit() {
    asm volatile("cp.async.commit_group;" ::: "memory");
}
template <int N>
__device__ __forceinline__ void cp_wait() {
    asm volatile("cp.async.wait_group %0;" :: "n"(N) : "memory");
}
__device__ __forceinline__ void ldsm4(uint32_t r[4], uint32_t addr) {
    asm volatile("ldmatrix.sync.aligned.m8n8.x4.shared.b16 {%0,%1,%2,%3}, [%4];"
                 : "=r"(r[0]), "=r"(r[1]), "=r"(r[2]), "=r"(r[3]) : "r"(addr));
}
__device__ __forceinline__ void ldsm4t(uint32_t r[4], uint32_t addr) {
    asm volatile("ldmatrix.sync.aligned.m8n8.x4.trans.shared.b16 {%0,%1,%2,%3}, [%4];"
                 : "=r"(r[0]), "=r"(r[1]), "=r"(r[2]), "=r"(r[3]) : "r"(addr));
}
__device__ __forceinline__ void mma16816(float d[4], const uint32_t a[4],
                                         uint32_t b0, uint32_t b1) {
    asm volatile(
        "mma.sync.aligned.m16n8k16.row.col.f32.f16.f16.f32 "
        "{%0,%1,%2,%3}, {%4,%5,%6,%7}, {%8,%9}, {%0,%1,%2,%3};"
        : "+f"(d[0]), "+f"(d[1]), "+f"(d[2]), "+f"(d[3])
        : "r"(a[0]), "r"(a[1]), "r"(a[2]), "r"(a[3]), "r"(b0), "r"(b1));
}
__device__ __forceinline__ uint32_t h2pack(float x, float y) {
    __half2 h = __floats2half2_rn(x, y);
    return *(uint32_t*)&h;
}

// ---------------------------------------------------------------------------
// Converters
// ---------------------------------------------------------------------------
__global__ __launch_bounds__(256) void f2h(const float* __restrict__ in,
                                           __half* __restrict__ out, int n)
{
    const int i = (blockIdx.x * 256 + threadIdx.x) * 8;
    if (i < n) {
        float4 a = *(const float4*)(in + i);
        float4 b = *(const float4*)(in + i + 4);
        __half2 h[4];
        h[0] = __floats2half2_rn(a.x, a.y);
        h[1] = __floats2half2_rn(a.z, a.w);
        h[2] = __floats2half2_rn(b.x, b.y);
        h[3] = __floats2half2_rn(b.z, b.w);
        *(uint4*)(out + i) = *(uint4*)h;
    }
}

__global__ __launch_bounds__(256) void transpose_f2h4(
    const float* __restrict__ W0, const float* __restrict__ W1,
    const float* __restrict__ W2, const float* __restrict__ W3,
    __half* __restrict__ outbase)
{
    __shared__ float t[32][33];
    const int z = blockIdx.z;
    const float* in = (z == 0) ? W0 : (z == 1) ? W1 : (z == 2) ? W2 : W3;
    __half* out = outbase + (size_t)z * D_MODEL * D_MODEL;
    const int bx = blockIdx.x * 32, by = blockIdx.y * 32;
    const int x = threadIdx.x & 31, y0 = threadIdx.x >> 5;
#pragma unroll
    for (int i = 0; i < 32; i += 8)
        t[y0 + i][x] = in[(size_t)(by + y0 + i) * D_MODEL + bx + x];
    __syncthreads();
#pragma unroll
    for (int i = 0; i < 32; i += 8)
        out[(size_t)(bx + y0 + i) * D_MODEL + by + x] = __float2half(t[x][y0 + i]);
}

// ---------------------------------------------------------------------------
// fp16 tensor-core GEMM, 3-stage cp.async pipeline, one barrier per K-iter.
// Ordering per iteration: wait(stage it) -> barrier -> issue load(it+2) ->
// compute(it). Load target (it+2)%3 never collides with compute (it)%3 nor a
// runahead warp's (it+1)%3; laggards are fenced by the barrier.
// ---------------------------------------------------------------------------
#define BM 128
#define BN 128
#define BKH 32
#define LDH 40
#define TILE_H (128 * LDH)
#define STAGE_B (2 * TILE_H * 2)        /* 20480 B */
#define GEMM_SMEM (3 * STAGE_B)         /* 61440 B */
#define GK 1024

template <bool OH>
__global__ __launch_bounds__(256) void gemm_h(
    const __half* __restrict__ A, const __half* __restrict__ BT,
    const float* __restrict__ bias0, const float* __restrict__ bias1,
    const float* __restrict__ bias2,
    float* __restrict__ Cf,
    __half* __restrict__ H0, __half* __restrict__ H1, __half* __restrict__ H2)
{
    extern __shared__ __align__(16) char sm[];
    const uint32_t sb = smem_u32(sm);

    const int tid   = threadIdx.x;
    const int wid   = tid >> 5;
    const int lane  = tid & 31;
    const int wm    = wid >> 1;
    const int wn    = wid & 1;
    const int row0  = blockIdx.y * BM;
    const int col0g = blockIdx.x * BN;
    const int seg   = col0g >> 10;
    const int colL  = col0g & 1023;
    const float* bias = (seg == 0) ? bias0 : (seg == 1) ? bias1 : bias2;
    __half* Hout      = (seg == 0) ? H0    : (seg == 1) ? H1    : H2;

    wmma::fragment<wmma::accumulator, 16, 16, 16, float> acc[2][4];
#pragma unroll
    for (int i = 0; i < 2; i++)
#pragma unroll
        for (int j = 0; j < 4; j++) wmma::fill_fragment(acc[i][j], 0.f);

    const int r0 = tid >> 2;
    const int c0 = (tid & 3) * 8;

    auto load_stage = [&](int k0, int s) {
        const uint32_t abase = sb + s * STAGE_B;
        const uint32_t bbase = abase + TILE_H * 2;
#pragma unroll
        for (int i = 0; i < 2; i++) {
            const int r = r0 + i * 64;
            cp_async16(abase + (r * LDH + c0) * 2,
                       A + (size_t)(row0 + r) * GK + k0 + c0);
        }
#pragma unroll
        for (int i = 0; i < 2; i++) {
            const int r = r0 + i * 64;
            cp_async16(bbase + (r * LDH + c0) * 2,
                       BT + (size_t)(col0g + r) * GK + k0 + c0);
        }
        cp_commit();
    };

    load_stage(0, 0);
    load_stage(BKH, 1);

    const int NIT = GK / BKH;   // 32
    int sc = 0;                 // compute stage
    int sl = 2;                 // next load stage
    for (int it = 0; it < NIT; it++) {
        if (it + 1 < NIT) cp_wait<1>();   // pending {it, it+1} -> group it done
        else              cp_wait<0>();
        __syncthreads();                  // all warps done with stage (it-1)%3

        if (it + 2 < NIT) {
            load_stage((it + 2) * BKH, sl);
            sl = (sl + 1) % 3;
        }

        const __half* smA = (const __half*)(sm + sc * STAGE_B);
        const __half* smB = smA + TILE_H;

#pragma unroll
        for (int kk = 0; kk < BKH; kk += 16) {
            wmma::fragment<wmma::matrix_a, 16, 16, 16, __half, wmma::row_major> af[2];
            wmma::fragment<wmma::matrix_b, 16, 16, 16, __half, wmma::col_major> bf[4];
#pragma unroll
            for (int i = 0; i < 2; i++)
                wmma::load_matrix_sync(af[i], smA + (wm * 32 + i * 16) * LDH + kk, LDH);
#pragma unroll
            for (int j = 0; j < 4; j++)
                wmma::load_matrix_sync(bf[j], smB + (wn * 64 + j * 16) * LDH + kk, LDH);
#pragma unroll
            for (int i = 0; i < 2; i++)
#pragma unroll
                for (int j = 0; j < 4; j++)
                    wmma::mma_sync(acc[i][j], af[i], bf[j], acc[i][j]);
        }
        sc = (sc + 1) % 3;
    }
    __syncthreads();   // smem reuse for epilogue staging

    float* Stg = (float*)sm + wid * 16 * 64;
    const int cb = wn * 64;
    const float bx = bias[colL + cb + lane * 2];
    const float by = bias[colL + cb + lane * 2 + 1];
#pragma unroll
    for (int i = 0; i < 2; i++) {
#pragma unroll
        for (int j = 0; j < 4; j++)
            wmma::store_matrix_sync(Stg + j * 16, acc[i][j], 64,
                                    wmma::mem_row_major);
        __syncwarp();
        const int rbase = row0 + wm * 32 + i * 16;
#pragma unroll
        for (int rr = 0; rr < 16; rr++) {
            float2 v = *(float2*)&Stg[rr * 64 + lane * 2];
            if (OH) {
                *(__half2*)&Hout[(size_t)(rbase + rr) * D_MODEL + colL + cb + lane * 2]
                    = __floats2half2_rn(v.x + bx, v.y + by);
            } else {
                float2 o; o.x = v.x + bx; o.y = v.y + by;
                *(float2*)&Cf[(size_t)(rbase + rr) * D_MODEL + colL + cb + lane * 2] = o;
            }
        }
        __syncwarp();
    }
}

// ---------------------------------------------------------------------------
// FA2-style causal attention with log2-domain softmax (register-resident).
// CTA = 128 Q rows, 8 warps x 16 rows. KV tiles of 64, cp.async double-buffer.
// ---------------------------------------------------------------------------
#define ALD 72
#define KVT_B (64 * ALD * 2)
#define AQ_OFF (4 * KVT_B)
#define ATT_SMEM (AQ_OFF + 128 * ALD * 2)   /* 55296 */
#define SCL2 0.18033688f                    /* 0.125 * log2(e) */

__global__ __launch_bounds__(256, 2) void attn_mma(
    const __half* __restrict__ q, const __half* __restrict__ k,
    const __half* __restrict__ v, __half* __restrict__ o)
{
    extern __shared__ __align__(16) char sm[];
    const uint32_t sb = smem_u32(sm);

    const int tid  = threadIdx.x;
    const int lane = tid & 31;
    const int w    = tid >> 5;
    const int qt   = (gridDim.x - 1) - blockIdx.x;
    const int bh   = blockIdx.y;
    const int b    = bh >> 4;
    const int h    = bh & 15;
    const int qbase = qt * 128;

    const __half* qp = q + ((size_t)b * SEQ + qbase) * D_MODEL + h * HDIM;

#pragma unroll
    for (int i = 0; i < 4; i++) {
        const int idx = tid + i * 256;
        const int r = idx >> 3, c8 = (idx & 7) * 8;
        cp_async16(sb + AQ_OFF + (r * ALD + c8) * 2, qp + (size_t)r * D_MODEL + c8);
    }
    cp_commit();

    auto load_kv = [&](int kt, int s) {
        const size_t krow = (size_t)b * SEQ + kt * 64;
        const __half* kp = k + krow * D_MODEL + h * HDIM;
        const __half* vp = v + krow * D_MODEL + h * HDIM;
        const uint32_t kb = sb + s * 2 * KVT_B;
        const uint32_t vb = kb + KVT_B;
#pragma unroll
        for (int i = 0; i < 2; i++) {
            const int idx = tid + i * 256;
            const int r = idx >> 3, c8 = (idx & 7) * 8;
            cp_async16(kb + (r * ALD + c8) * 2, kp + (size_t)r * D_MODEL + c8);
            cp_async16(vb + (r * ALD + c8) * 2, vp + (size_t)r * D_MODEL + c8);
        }
        cp_commit();
    };
    load_kv(0, 0);

    const int lrow = ((lane >> 3) & 1) * 8 + (lane & 7);
    const int lcol = (lane >> 4) * 8;

    cp_wait<1>();
    __syncthreads();

    uint32_t qa[4][4];
#pragma unroll
    for (int kk = 0; kk < 4; kk++)
        ldsm4(qa[kk], sb + AQ_OFF +
              ((w * 16 + lrow) * ALD + kk * 16 + lcol) * 2);

    float oacc[8][4];
#pragma unroll
    for (int j = 0; j < 8; j++)
#pragma unroll
        for (int e = 0; e < 4; e++) oacc[j][e] = 0.f;
    float m0 = -1e30f, m1 = -1e30f, l0 = 0.f, l1 = 0.f;

    const int wrow0 = qbase + w * 16;
    const int ntiles = 2 * qt + 2;

    for (int kt = 0; kt < ntiles; kt++) {
        const int s = kt & 1;
        cp_wait<0>();
        __syncthreads();
        if (kt + 1 < ntiles) load_kv(kt + 1, s ^ 1);

        if (kt * 64 <= wrow0 + 15) {
            const uint32_t kbb = sb + s * 2 * KVT_B;
            const uint32_t vbb = kbb + KVT_B;

            // ---- S = Q @ K^T ----
            float sacc[8][4];
#pragma unroll
            for (int j = 0; j < 8; j++)
#pragma unroll
                for (int e = 0; e < 4; e++) sacc[j][e] = 0.f;
#pragma unroll
            for (int kk = 0; kk < 4; kk++)
#pragma unroll
                for (int jj = 0; jj < 4; jj++) {
                    uint32_t kb4[4];
                    ldsm4(kb4, kbb + ((jj * 16 + lrow) * ALD + kk * 16 + lcol) * 2);
                    mma16816(sacc[2 * jj],     qa[kk], kb4[0], kb4[2]);
                    mma16816(sacc[2 * jj + 1], qa[kk], kb4[1], kb4[3]);
                }

            // ---- softmax in log2 domain ----
#pragma unroll
            for (int j = 0; j < 8; j++)
#pragma unroll
                for (int e = 0; e < 4; e++) sacc[j][e] *= SCL2;

            if (kt * 64 + 63 > wrow0) {
                const int colb = kt * 64 + (lane & 3) * 2;
                const int r0g  = wrow0 + (lane >> 2);
#pragma unroll
                for (int j = 0; j < 8; j++) {
                    const int c = colb + j * 8;
                    if (c     > r0g)     sacc[j][0] = -1e30f;
                    if (c + 1 > r0g)     sacc[j][1] = -1e30f;
                    if (c     > r0g + 8) sacc[j][2] = -1e30f;
                    if (c + 1 > r0g + 8) sacc[j][3] = -1e30f;
                }
            }

            float mx0 = sacc[0][0], mx1 = sacc[0][2];
#pragma unroll
            for (int j = 0; j < 8; j++) {
                mx0 = fmaxf(mx0, fmaxf(sacc[j][0], sacc[j][1]));
                mx1 = fmaxf(mx1, fmaxf(sacc[j][2], sacc[j][3]));
            }
            mx0 = fmaxf(mx0, __shfl_xor_sync(0xffffffffu, mx0, 1));
            mx0 = fmaxf(mx0, __shfl_xor_sync(0xffffffffu, mx0, 2));
            mx1 = fmaxf(mx1, __shfl_xor_sync(0xffffffffu, mx1, 1));
            mx1 = fmaxf(mx1, __shfl_xor_sync(0xffffffffu, mx1, 2));

            const float mn0 = fmaxf(m0, mx0);
            const float mn1 = fmaxf(m1, mx1);
            const float a0 = exp2f(m0 - mn0);
            const float a1 = exp2f(m1 - mn1);
            m0 = mn0; m1 = mn1;

            float s0 = 0.f, s1 = 0.f;
#pragma unroll
            for (int j = 0; j < 8; j++) {
                sacc[j][0] = exp2f(sacc[j][0] - mn0);
                sacc[j][1] = exp2f(sacc[j][1] - mn0);
                sacc[j][2] = exp2f(sacc[j][2] - mn1);
                sacc[j][3] = exp2f(sacc[j][3] - mn1);
                s0 += sacc[j][0] + sacc[j][1];
                s1 += sacc[j][2] + sacc[j][3];
            }
            s0 += __shfl_xor_sync(0xffffffffu, s0, 1);
            s0 += __shfl_xor_sync(0xffffffffu, s0, 2);
            s1 += __shfl_xor_sync(0xffffffffu, s1, 1);
            s1 += __shfl_xor_sync(0xffffffffu, s1, 2);
            l0 = l0 * a0 + s0;
            l1 = l1 * a1 + s1;

#pragma unroll
            for (int j = 0; j < 8; j++) {
                oacc[j][0] *= a0; oacc[j][1] *= a0;
                oacc[j][2] *= a1; oacc[j][3] *= a1;
            }

            // ---- O += P @ V ----
#pragma unroll
            for (int t = 0; t < 4; t++) {
                uint32_t pa[4];
                pa[0] = h2pack(sacc[2 * t][0],     sacc[2 * t][1]);
                pa[1] = h2pack(sacc[2 * t][2],     sacc[2 * t][3]);
                pa[2] = h2pack(sacc[2 * t + 1][0], sacc[2 * t + 1][1]);
                pa[3] = h2pack(sacc[2 * t + 1][2], sacc[2 * t + 1][3]);
#pragma unroll
                for (int jj = 0; jj < 4; jj++) {
                    uint32_t vb4[4];
                    ldsm4t(vb4, vbb + ((t * 16 + lrow) * ALD + jj * 16 + lcol) * 2);
                    mma16816(oacc[2 * jj],     pa, vb4[0], vb4[1]);
                    mma16816(oacc[2 * jj + 1], pa, vb4[2], vb4[3]);
                }
            }
        }
    }

    // ---- epilogue ----
    const float i0 = 1.f / l0;
    const float i1 = 1.f / l1;
    const int r0g = qbase + w * 16 + (lane >> 2);
    __half* o0 = o + ((size_t)b * SEQ + r0g) * D_MODEL + h * HDIM + (lane & 3) * 2;
    __half* o1 = o0 + 8 * D_MODEL;
#pragma unroll
    for (int j = 0; j < 8; j++) {
        *(__half2*)(o0 + j * 8) = __floats2half2_rn(oacc[j][0] * i0, oacc[j][1] * i0);
        *(__half2*)(o1 + j * 8) = __floats2half2_rn(oacc[j][2] * i1, oacc[j][3] * i1);
    }
}

// ---------------------------------------------------------------------------
extern "C" void kernel_launch(void* const* d_in, const int* in_sizes, int n_in,
                              void* d_out, int out_size)
{
    (void)in_sizes; (void)n_in; (void)out_size;
    const float* x  = (const float*)d_in[0];
    const float* Wq = (const float*)d_in[1];
    const float* bq = (const float*)d_in[2];
    const float* Wk = (const float*)d_in[3];
    const float* bk = (const float*)d_in[4];
    const float* Wv = (const float*)d_in[5];
    const float* bv = (const float*)d_in[6];
    const float* Wo = (const float*)d_in[7];
    const float* bo = (const float*)d_in[8];
    float* out = (float*)d_out;

    __half *gqh, *gkh, *gvh, *gxh, *goh, *gwth;
    cudaGetSymbolAddress((void**)&gqh, g_qh);
    cudaGetSymbolAddress((void**)&gkh, g_kh);
    cudaGetSymbolAddress((void**)&gvh, g_vh);
    cudaGetSymbolAddress((void**)&gxh, g_xh);
    cudaGetSymbolAddress((void**)&goh, g_oh);
    cudaGetSymbolAddress((void**)&gwth, g_wth);
    __half* wto = gwth + 3 * (size_t)D_MODEL * D_MODEL;

    const int NELEM = MROWS * D_MODEL;

    cudaFuncSetAttribute(attn_mma,
                         cudaFuncAttributeMaxDynamicSharedMemorySize, ATT_SMEM);
    cudaFuncSetAttribute(gemm_h<true>,
                         cudaFuncAttributeMaxDynamicSharedMemorySize, GEMM_SMEM);
    cudaFuncSetAttribute(gemm_h<false>,
                         cudaFuncAttributeMaxDynamicSharedMemorySize, GEMM_SMEM);

    dim3 gt(32, 32, 4);
    transpose_f2h4<<<gt, 256>>>(Wq, Wk, Wv, Wo, gwth);
    f2h<<<NELEM / (256 * 8), 256>>>(x, gxh, NELEM);

    dim3 gqkv(3 * D_MODEL / BN, MROWS / BM);   // (24, 64)
    gemm_h<true><<<gqkv, 256, GEMM_SMEM>>>(gxh, gwth, bq, bk, bv,
                                           nullptr, gqh, gkh, gvh);

    dim3 ga(SEQ / 128, BATCH * HEADS);         // (16, 64)
    attn_mma<<<ga, 256, ATT_SMEM>>>(gqh, gkh, gvh, goh);

    dim3 go(D_MODEL / BN, MROWS / BM);         // (8, 64)
    gemm_h<false><<<go, 256, GEMM_SMEM>>>(goh, wto, bo, nullptr, nullptr,
                                          out, nullptr, nullptr, nullptr);
}

// round 13
// speedup vs baseline: 1.5606x; 1.5606x over previous
#include <cuda_runtime.h>
#include <cuda_fp16.h>
#include <mma.h>
#include <cstddef>
#include <cstdint>

using namespace nvcuda;

#define D_MODEL 1024
#define SEQ     2048
#define BATCH   4
#define HEADS   16
#define HDIM    64
#define MROWS   (BATCH * SEQ)   /* 8192 */

// Scratch (alloc-free rule: __device__ globals)
__device__ __half g_qh[MROWS * D_MODEL];
__device__ __half g_kh[MROWS * D_MODEL];
__device__ __half g_vh[MROWS * D_MODEL];
__device__ __half g_xh[MROWS * D_MODEL];
__device__ __half g_oh[MROWS * D_MODEL];
__device__ __half g_wth[4 * D_MODEL * D_MODEL];   // transposed half weights (q,k,v,o)

// ---------------------------------------------------------------------------
// helpers
// ---------------------------------------------------------------------------
__device__ __forceinline__ uint32_t smem_u32(const void* p) {
    uint32_t a;
    asm("{ .reg .u64 t; cvta.to.shared.u64 t, %1; cvt.u32.u64 %0, t; }"
        : "=r"(a) : "l"(p));
    return a;
}
__device__ __forceinline__ void cp_async16(uint32_t dst, const void* src) {
    asm volatile("cp.async.cg.shared.global [%0], [%1], 16;"
                 :: "r"(dst), "l"(__cvta_generic_to_global(src)) : "memory");
}
__device__ __forceinline__ void cp_commit() {
    asm volatile("cp.async.commit_group;" ::: "memory");
}
template <int N>
__device__ __forceinline__ void cp_wait() {
    asm volatile("cp.async.wait_group %0;" :: "n"(N) : "memory");
}
__device__ __forceinline__ void ldsm4(uint32_t r[4], uint32_t addr) {
    asm volatile("ldmatrix.sync.aligned.m8n8.x4.shared.b16 {%0,%1,%2,%3}, [%4];"
                 : "=r"(r[0]), "=r"(r[1]), "=r"(r[2]), "=r"(r[3]) : "r"(addr));
}
__device__ __forceinline__ void ldsm4t(uint32_t r[4], uint32_t addr) {
    asm volatile("ldmatrix.sync.aligned.m8n8.x4.trans.shared.b16 {%0,%1,%2,%3}, [%4];"
                 : "=r"(r[0]), "=r"(r[1]), "=r"(r[2]), "=r"(r[3]) : "r"(addr));
}
__device__ __forceinline__ void mma16816(float d[4], const uint32_t a[4],
                                         uint32_t b0, uint32_t b1) {
    asm volatile(
        "mma.sync.aligned.m16n8k16.row.col.f32.f16.f16.f32 "
        "{%0,%1,%2,%3}, {%4,%5,%6,%7}, {%8,%9}, {%0,%1,%2,%3};"
        : "+f"(d[0]), "+f"(d[1]), "+f"(d[2]), "+f"(d[3])
        : "r"(a[0]), "r"(a[1]), "r"(a[2]), "r"(a[3]), "r"(b0), "r"(b1));
}
__device__ __forceinline__ uint32_t h2pack(float x, float y) {
    __half2 h = __floats2half2_rn(x, y);
    return *(uint32_t*)&h;
}
// MUFU EX2 directly (2^x). NOT exp2f (accurate libm path w/o fast-math).
__device__ __forceinline__ float ex2(float x) {
    float y;
    asm("ex2.approx.f32 %0, %1;" : "=f"(y) : "f"(x));
    return y;
}

// ---------------------------------------------------------------------------
// Converters
// ---------------------------------------------------------------------------
__global__ __launch_bounds__(256) void f2h(const float* __restrict__ in,
                                           __half* __restrict__ out, int n)
{
    const int i = (blockIdx.x * 256 + threadIdx.x) * 8;
    if (i < n) {
        float4 a = *(const float4*)(in + i);
        float4 b = *(const float4*)(in + i + 4);
        __half2 h[4];
        h[0] = __floats2half2_rn(a.x, a.y);
        h[1] = __floats2half2_rn(a.z, a.w);
        h[2] = __floats2half2_rn(b.x, b.y);
        h[3] = __floats2half2_rn(b.z, b.w);
        *(uint4*)(out + i) = *(uint4*)h;
    }
}

__global__ __launch_bounds__(256) void transpose_f2h4(
    const float* __restrict__ W0, const float* __restrict__ W1,
    const float* __restrict__ W2, const float* __restrict__ W3,
    __half* __restrict__ outbase)
{
    __shared__ float t[32][33];
    const int z = blockIdx.z;
    const float* in = (z == 0) ? W0 : (z == 1) ? W1 : (z == 2) ? W2 : W3;
    __half* out = outbase + (size_t)z * D_MODEL * D_MODEL;
    const int bx = blockIdx.x * 32, by = blockIdx.y * 32;
    const int x = threadIdx.x & 31, y0 = threadIdx.x >> 5;
#pragma unroll
    for (int i = 0; i < 32; i += 8)
        t[y0 + i][x] = in[(size_t)(by + y0 + i) * D_MODEL + bx + x];
    __syncthreads();
#pragma unroll
    for (int i = 0; i < 32; i += 8)
        out[(size_t)(bx + y0 + i) * D_MODEL + by + x] = __float2half(t[x][y0 + i]);
}

// ---------------------------------------------------------------------------
// fp16 tensor-core GEMM — round-10 proven version (2-stage, static smem).
// C = A[M,K] @ BT[N,K]^T + bias. 128x128x32 tile, 256 threads (8 warps, 4x2).
// ---------------------------------------------------------------------------
#define BM 128
#define BN 128
#define BKH 32
#define LDH 40
#define TILE_H (128 * LDH)
#define STAGE_B (2 * TILE_H * 2)
#define GK 1024

template <bool OH>
__global__ __launch_bounds__(256) void gemm_h(
    const __half* __restrict__ A, const __half* __restrict__ BT,
    const float* __restrict__ bias0, const float* __restrict__ bias1,
    const float* __restrict__ bias2,
    float* __restrict__ Cf,
    __half* __restrict__ H0, __half* __restrict__ H1, __half* __restrict__ H2)
{
    __shared__ __align__(16) char sm[2 * STAGE_B];
    const uint32_t sb = smem_u32(sm);

    const int tid   = threadIdx.x;
    const int wid   = tid >> 5;
    const int lane  = tid & 31;
    const int wm    = wid >> 1;
    const int wn    = wid & 1;
    const int row0  = blockIdx.y * BM;
    const int col0g = blockIdx.x * BN;
    const int seg   = col0g >> 10;
    const int colL  = col0g & 1023;
    const float* bias = (seg == 0) ? bias0 : (seg == 1) ? bias1 : bias2;
    __half* Hout      = (seg == 0) ? H0    : (seg == 1) ? H1    : H2;

    wmma::fragment<wmma::accumulator, 16, 16, 16, float> acc[2][4];
#pragma unroll
    for (int i = 0; i < 2; i++)
#pragma unroll
        for (int j = 0; j < 4; j++) wmma::fill_fragment(acc[i][j], 0.f);

    const int r0 = tid >> 2;
    const int c0 = (tid & 3) * 8;

    auto load_stage = [&](int k0, int s) {
        const uint32_t abase = sb + s * STAGE_B;
        const uint32_t bbase = abase + TILE_H * 2;
#pragma unroll
        for (int i = 0; i < 2; i++) {
            const int r = r0 + i * 64;
            cp_async16(abase + (r * LDH + c0) * 2,
                       A + (size_t)(row0 + r) * GK + k0 + c0);
        }
#pragma unroll
        for (int i = 0; i < 2; i++) {
            const int r = r0 + i * 64;
            cp_async16(bbase + (r * LDH + c0) * 2,
                       BT + (size_t)(col0g + r) * GK + k0 + c0);
        }
        cp_commit();
    };

    load_stage(0, 0);

    const int NIT = GK / BKH;
    for (int it = 0; it < NIT; it++) {
        const int s = it & 1;
        if (it + 1 < NIT) { load_stage((it + 1) * BKH, s ^ 1); cp_wait<1>(); }
        else              { cp_wait<0>(); }
        __syncthreads();

        const __half* smA = (const __half*)(sm + s * STAGE_B);
        const __half* smB = smA + TILE_H;

#pragma unroll
        for (int kk = 0; kk < BKH; kk += 16) {
            wmma::fragment<wmma::matrix_a, 16, 16, 16, __half, wmma::row_major> af[2];
            wmma::fragment<wmma::matrix_b, 16, 16, 16, __half, wmma::col_major> bf[4];
#pragma unroll
            for (int i = 0; i < 2; i++)
                wmma::load_matrix_sync(af[i], smA + (wm * 32 + i * 16) * LDH + kk, LDH);
#pragma unroll
            for (int j = 0; j < 4; j++)
                wmma::load_matrix_sync(bf[j], smB + (wn * 64 + j * 16) * LDH + kk, LDH);
#pragma unroll
            for (int i = 0; i < 2; i++)
#pragma unroll
                for (int j = 0; j < 4; j++)
                    wmma::mma_sync(acc[i][j], af[i], bf[j], acc[i][j]);
        }
        __syncthreads();
    }

    float* Stg = (float*)sm + wid * 16 * 64;
    const int cb = wn * 64;
    const float bx = bias[colL + cb + lane * 2];
    const float by = bias[colL + cb + lane * 2 + 1];
#pragma unroll
    for (int i = 0; i < 2; i++) {
#pragma unroll
        for (int j = 0; j < 4; j++)
            wmma::store_matrix_sync(Stg + j * 16, acc[i][j], 64,
                                    wmma::mem_row_major);
        __syncwarp();
        const int rbase = row0 + wm * 32 + i * 16;
#pragma unroll
        for (int rr = 0; rr < 16; rr++) {
            float2 v = *(float2*)&Stg[rr * 64 + lane * 2];
            if (OH) {
                *(__half2*)&Hout[(size_t)(rbase + rr) * D_MODEL + colL + cb + lane * 2]
                    = __floats2half2_rn(v.x + bx, v.y + by);
            } else {
                float2 o; o.x = v.x + bx; o.y = v.y + by;
                *(float2*)&Cf[(size_t)(rbase + rr) * D_MODEL + colL + cb + lane * 2] = o;
            }
        }
        __syncwarp();
    }
}

// ---------------------------------------------------------------------------
// FA2-style causal attention (round-10 proven loop) + log2 softmax via
// MUFU ex2.approx (strictly fewer ops than __expf, same HW unit).
// CTA = 128 Q rows, 8 warps x 16 rows. KV tiles of 64, cp.async double-buffer.
// ---------------------------------------------------------------------------
#define ALD 72
#define KVT_B (64 * ALD * 2)
#define AQ_OFF (4 * KVT_B)
#define ATT_SMEM (AQ_OFF + 128 * ALD * 2)   /* 55296 */
#define SCL2 0.18033688f                    /* 0.125 * log2(e) */

__global__ __launch_bounds__(256, 2) void attn_mma(
    const __half* __restrict__ q, const __half* __restrict__ k,
    const __half* __restrict__ v, __half* __restrict__ o)
{
    extern __shared__ __align__(16) char sm[];
    const uint32_t sb = smem_u32(sm);

    const int tid  = threadIdx.x;
    const int lane = tid & 31;
    const int w    = tid >> 5;
    const int qt   = (gridDim.x - 1) - blockIdx.x;
    const int bh   = blockIdx.y;
    const int b    = bh >> 4;
    const int h    = bh & 15;
    const int qbase = qt * 128;

    const __half* qp = q + ((size_t)b * SEQ + qbase) * D_MODEL + h * HDIM;

#pragma unroll
    for (int i = 0; i < 4; i++) {
        const int idx = tid + i * 256;
        const int r = idx >> 3, c8 = (idx & 7) * 8;
        cp_async16(sb + AQ_OFF + (r * ALD + c8) * 2, qp + (size_t)r * D_MODEL + c8);
    }
    cp_commit();

    auto load_kv = [&](int kt, int s) {
        const size_t krow = (size_t)b * SEQ + kt * 64;
        const __half* kp = k + krow * D_MODEL + h * HDIM;
        const __half* vp = v + krow * D_MODEL + h * HDIM;
        const uint32_t kb = sb + s * 2 * KVT_B;
        const uint32_t vb = kb + KVT_B;
#pragma unroll
        for (int i = 0; i < 2; i++) {
            const int idx = tid + i * 256;
            const int r = idx >> 3, c8 = (idx & 7) * 8;
            cp_async16(kb + (r * ALD + c8) * 2, kp + (size_t)r * D_MODEL + c8);
            cp_async16(vb + (r * ALD + c8) * 2, vp + (size_t)r * D_MODEL + c8);
        }
        cp_commit();
    };
    load_kv(0, 0);

    const int lrow = ((lane >> 3) & 1) * 8 + (lane & 7);
    const int lcol = (lane >> 4) * 8;

    cp_wait<1>();
    __syncthreads();

    uint32_t qa[4][4];
#pragma unroll
    for (int kk = 0; kk < 4; kk++)
        ldsm4(qa[kk], sb + AQ_OFF +
              ((w * 16 + lrow) * ALD + kk * 16 + lcol) * 2);

    float oacc[8][4];
#pragma unroll
    for (int j = 0; j < 8; j++)
#pragma unroll
        for (int e = 0; e < 4; e++) oacc[j][e] = 0.f;
    float m0 = -1e30f, m1 = -1e30f, l0 = 0.f, l1 = 0.f;

    const int wrow0 = qbase + w * 16;
    const int ntiles = 2 * qt + 2;

    for (int kt = 0; kt < ntiles; kt++) {
        const int s = kt & 1;
        cp_wait<0>();
        __syncthreads();
        if (kt + 1 < ntiles) load_kv(kt + 1, s ^ 1);

        if (kt * 64 <= wrow0 + 15) {
            const uint32_t kbb = sb + s * 2 * KVT_B;
            const uint32_t vbb = kbb + KVT_B;

            // ---- S = Q @ K^T ----
            float sacc[8][4];
#pragma unroll
            for (int j = 0; j < 8; j++)
#pragma unroll
                for (int e = 0; e < 4; e++) sacc[j][e] = 0.f;
#pragma unroll
            for (int kk = 0; kk < 4; kk++)
#pragma unroll
                for (int jj = 0; jj < 4; jj++) {
                    uint32_t kb4[4];
                    ldsm4(kb4, kbb + ((jj * 16 + lrow) * ALD + kk * 16 + lcol) * 2);
                    mma16816(sacc[2 * jj],     qa[kk], kb4[0], kb4[2]);
                    mma16816(sacc[2 * jj + 1], qa[kk], kb4[1], kb4[3]);
                }

            // ---- softmax in log2 domain (MUFU ex2) ----
#pragma unroll
            for (int j = 0; j < 8; j++)
#pragma unroll
                for (int e = 0; e < 4; e++) sacc[j][e] *= SCL2;

            if (kt * 64 + 63 > wrow0) {
                const int colb = kt * 64 + (lane & 3) * 2;
                const int r0g  = wrow0 + (lane >> 2);
#pragma unroll
                for (int j = 0; j < 8; j++) {
                    const int c = colb + j * 8;
                    if (c     > r0g)     sacc[j][0] = -1e30f;
                    if (c + 1 > r0g)     sacc[j][1] = -1e30f;
                    if (c     > r0g + 8) sacc[j][2] = -1e30f;
                    if (c + 1 > r0g + 8) sacc[j][3] = -1e30f;
                }
            }

            float mx0 = sacc[0][0], mx1 = sacc[0][2];
#pragma unroll
            for (int j = 0; j < 8; j++) {
                mx0 = fmaxf(mx0, fmaxf(sacc[j][0], sacc[j][1]));
                mx1 = fmaxf(mx1, fmaxf(sacc[j][2], sacc[j][3]));
            }
            mx0 = fmaxf(mx0, __shfl_xor_sync(0xffffffffu, mx0, 1));
            mx0 = fmaxf(mx0, __shfl_xor_sync(0xffffffffu, mx0, 2));
            mx1 = fmaxf(mx1, __shfl_xor_sync(0xffffffffu, mx1, 1));
            mx1 = fmaxf(mx1, __shfl_xor_sync(0xffffffffu, mx1, 2));

            const float mn0 = fmaxf(m0, mx0);
            const float mn1 = fmaxf(m1, mx1);
            const float a0 = ex2(m0 - mn0);
            const float a1 = ex2(m1 - mn1);
            m0 = mn0; m1 = mn1;

            float s0 = 0.f, s1 = 0.f;
#pragma unroll
            for (int j = 0; j < 8; j++) {
                sacc[j][0] = ex2(sacc[j][0] - mn0);
                sacc[j][1] = ex2(sacc[j][1] - mn0);
                sacc[j][2] = ex2(sacc[j][2] - mn1);
                sacc[j][3] = ex2(sacc[j][3] - mn1);
                s0 += sacc[j][0] + sacc[j][1];
                s1 += sacc[j][2] + sacc[j][3];
            }
            s0 += __shfl_xor_sync(0xffffffffu, s0, 1);
            s0 += __shfl_xor_sync(0xffffffffu, s0, 2);
            s1 += __shfl_xor_sync(0xffffffffu, s1, 1);
            s1 += __shfl_xor_sync(0xffffffffu, s1, 2);
            l0 = l0 * a0 + s0;
            l1 = l1 * a1 + s1;

#pragma unroll
            for (int j = 0; j < 8; j++) {
                oacc[j][0] *= a0; oacc[j][1] *= a0;
                oacc[j][2] *= a1; oacc[j][3] *= a1;
            }

            // ---- O += P @ V ----
#pragma unroll
            for (int t = 0; t < 4; t++) {
                uint32_t pa[4];
                pa[0] = h2pack(sacc[2 * t][0],     sacc[2 * t][1]);
                pa[1] = h2pack(sacc[2 * t][2],     sacc[2 * t][3]);
                pa[2] = h2pack(sacc[2 * t + 1][0], sacc[2 * t + 1][1]);
                pa[3] = h2pack(sacc[2 * t + 1][2], sacc[2 * t + 1][3]);
#pragma unroll
                for (int jj = 0; jj < 4; jj++) {
                    uint32_t vb4[4];
                    ldsm4t(vb4, vbb + ((t * 16 + lrow) * ALD + jj * 16 + lcol) * 2);
                    mma16816(oacc[2 * jj],     pa, vb4[0], vb4[1]);
                    mma16816(oacc[2 * jj + 1], pa, vb4[2], vb4[3]);
                }
            }
        }
    }

    // ---- epilogue ----
    const float i0 = 1.f / l0;
    const float i1 = 1.f / l1;
    const int r0g = qbase + w * 16 + (lane >> 2);
    __half* o0 = o + ((size_t)b * SEQ + r0g) * D_MODEL + h * HDIM + (lane & 3) * 2;
    __half* o1 = o0 + 8 * D_MODEL;
#pragma unroll
    for (int j = 0; j < 8; j++) {
        *(__half2*)(o0 + j * 8) = __floats2half2_rn(oacc[j][0] * i0, oacc[j][1] * i0);
        *(__half2*)(o1 + j * 8) = __floats2half2_rn(oacc[j][2] * i1, oacc[j][3] * i1);
    }
}

// ---------------------------------------------------------------------------
extern "C" void kernel_launch(void* const* d_in, const int* in_sizes, int n_in,
                              void* d_out, int out_size)
{
    (void)in_sizes; (void)n_in; (void)out_size;
    const float* x  = (const float*)d_in[0];
    const float* Wq = (const float*)d_in[1];
    const float* bq = (const float*)d_in[2];
    const float* Wk = (const float*)d_in[3];
    const float* bk = (const float*)d_in[4];
    const float* Wv = (const float*)d_in[5];
    const float* bv = (const float*)d_in[6];
    const float* Wo = (const float*)d_in[7];
    const float* bo = (const float*)d_in[8];
    float* out = (float*)d_out;

    __half *gqh, *gkh, *gvh, *gxh, *goh, *gwth;
    cudaGetSymbolAddress((void**)&gqh, g_qh);
    cudaGetSymbolAddress((void**)&gkh, g_kh);
    cudaGetSymbolAddress((void**)&gvh, g_vh);
    cudaGetSymbolAddress((void**)&gxh, g_xh);
    cudaGetSymbolAddress((void**)&goh, g_oh);
    cudaGetSymbolAddress((void**)&gwth, g_wth);
    __half* wto = gwth + 3 * (size_t)D_MODEL * D_MODEL;

    const int NELEM = MROWS * D_MODEL;

    cudaFuncSetAttribute(attn_mma,
                         cudaFuncAttributeMaxDynamicSharedMemorySize, ATT_SMEM);

    dim3 gt(32, 32, 4);
    transpose_f2h4<<<gt, 256>>>(Wq, Wk, Wv, Wo, gwth);
    f2h<<<NELEM / (256 * 8), 256>>>(x, gxh, NELEM);

    dim3 gqkv(3 * D_MODEL / BN, MROWS / BM);   // (24, 64)
    gemm_h<true><<<gqkv, 256>>>(gxh, gwth, bq, bk, bv,
                                nullptr, gqh, gkh, gvh);

    dim3 ga(SEQ / 128, BATCH * HEADS);         // (16, 64)
    attn_mma<<<ga, 256, ATT_SMEM>>>(gqh, gkh, gvh, goh);

    dim3 go(D_MODEL / BN, MROWS / BM);         // (8, 64)
    gemm_h<false><<<go, 256>>>(goh, wto, bo, nullptr, nullptr,
                               out, nullptr, nullptr, nullptr);
}

// round 15
// speedup vs baseline: 1.6450x; 1.0541x over previous
#include <cuda_runtime.h>
#include <cuda_fp16.h>
#include <mma.h>
#include <cstddef>
#include <cstdint>

using namespace nvcuda;

#define D_MODEL 1024
#define SEQ     2048
#define BATCH   4
#define HEADS   16
#define HDIM    64
#define MROWS   (BATCH * SEQ)   /* 8192 */

// Scratch (alloc-free rule: __device__ globals)
__device__ __half g_qh[MROWS * D_MODEL];
__device__ __half g_kh[MROWS * D_MODEL];
__device__ __half g_vh[MROWS * D_MODEL];
__device__ __half g_xh[MROWS * D_MODEL];
__device__ __half g_oh[MROWS * D_MODEL];
__device__ __half g_wth[4 * D_MODEL * D_MODEL];   // transposed half weights (q,k,v,o)

// ---------------------------------------------------------------------------
// helpers
// ---------------------------------------------------------------------------
__device__ __forceinline__ uint32_t smem_u32(const void* p) {
    uint32_t a;
    asm("{ .reg .u64 t; cvta.to.shared.u64 t, %1; cvt.u32.u64 %0, t; }"
        : "=r"(a) : "l"(p));
    return a;
}
__device__ __forceinline__ void cp_async16(uint32_t dst, const void* src) {
    asm volatile("cp.async.cg.shared.global [%0], [%1], 16;"
                 :: "r"(dst), "l"(__cvta_generic_to_global(src)) : "memory");
}
__device__ __forceinline__ void cp_commit() {
    asm volatile("cp.async.commit_group;" ::: "memory");
}
template <int N>
__device__ __forceinline__ void cp_wait() {
    asm volatile("cp.async.wait_group %0;" :: "n"(N) : "memory");
}
__device__ __forceinline__ void ldsm4(uint32_t r[4], uint32_t addr) {
    asm volatile("ldmatrix.sync.aligned.m8n8.x4.shared.b16 {%0,%1,%2,%3}, [%4];"
                 : "=r"(r[0]), "=r"(r[1]), "=r"(r[2]), "=r"(r[3]) : "r"(addr));
}
__device__ __forceinline__ void ldsm4t(uint32_t r[4], uint32_t addr) {
    asm volatile("ldmatrix.sync.aligned.m8n8.x4.trans.shared.b16 {%0,%1,%2,%3}, [%4];"
                 : "=r"(r[0]), "=r"(r[1]), "=r"(r[2]), "=r"(r[3]) : "r"(addr));
}
__device__ __forceinline__ void mma16816(float d[4], const uint32_t a[4],
                                         uint32_t b0, uint32_t b1) {
    asm volatile(
        "mma.sync.aligned.m16n8k16.row.col.f32.f16.f16.f32 "
        "{%0,%1,%2,%3}, {%4,%5,%6,%7}, {%8,%9}, {%0,%1,%2,%3};"
        : "+f"(d[0]), "+f"(d[1]), "+f"(d[2]), "+f"(d[3])
        : "r"(a[0]), "r"(a[1]), "r"(a[2]), "r"(a[3]), "r"(b0), "r"(b1));
}
__device__ __forceinline__ uint32_t h2pack(float x, float y) {
    __half2 h = __floats2half2_rn(x, y);
    return *(uint32_t*)&h;
}
// MUFU EX2 directly (2^x). NOT exp2f (accurate libm path w/o fast-math).
__device__ __forceinline__ float ex2(float x) {
    float y;
    asm("ex2.approx.f32 %0, %1;" : "=f"(y) : "f"(x));
    return y;
}

// ---------------------------------------------------------------------------
// Converters
// ---------------------------------------------------------------------------
__global__ __launch_bounds__(256) void f2h(const float* __restrict__ in,
                                           __half* __restrict__ out, int n)
{
    const int i = (blockIdx.x * 256 + threadIdx.x) * 8;
    if (i < n) {
        float4 a = *(const float4*)(in + i);
        float4 b = *(const float4*)(in + i + 4);
        __half2 h[4];
        h[0] = __floats2half2_rn(a.x, a.y);
        h[1] = __floats2half2_rn(a.z, a.w);
        h[2] = __floats2half2_rn(b.x, b.y);
        h[3] = __floats2half2_rn(b.z, b.w);
        *(uint4*)(out + i) = *(uint4*)h;
    }
}

__global__ __launch_bounds__(256) void transpose_f2h4(
    const float* __restrict__ W0, const float* __restrict__ W1,
    const float* __restrict__ W2, const float* __restrict__ W3,
    __half* __restrict__ outbase)
{
    __shared__ float t[32][33];
    const int z = blockIdx.z;
    const float* in = (z == 0) ? W0 : (z == 1) ? W1 : (z == 2) ? W2 : W3;
    __half* out = outbase + (size_t)z * D_MODEL * D_MODEL;
    const int bx = blockIdx.x * 32, by = blockIdx.y * 32;
    const int x = threadIdx.x & 31, y0 = threadIdx.x >> 5;
#pragma unroll
    for (int i = 0; i < 32; i += 8)
        t[y0 + i][x] = in[(size_t)(by + y0 + i) * D_MODEL + bx + x];
    __syncthreads();
#pragma unroll
    for (int i = 0; i < 32; i += 8)
        out[(size_t)(bx + y0 + i) * D_MODEL + by + x] = __float2half(t[x][y0 + i]);
}

// ---------------------------------------------------------------------------
// fp16 tensor-core GEMM, 2-stage cp.async, BKH=64 (half the barriers of BKH=32).
// C = A[M,K] @ BT[N,K]^T + bias. 128x128x64 tile, 256 threads (8 warps, 4x2).
// Dynamic smem: 2 stages x (A 128x72 + B 128x72 halves) = 73728 B.
// ---------------------------------------------------------------------------
#define BM 128
#define BN 128
#define BKH 64
#define LDH 72
#define TILE_H (128 * LDH)                 /* halves per operand tile */
#define STAGE_B (2 * TILE_H * 2)           /* 36864 B */
#define GEMM_SMEM (2 * STAGE_B)            /* 73728 B */
#define GK 1024

template <bool OH>
__global__ __launch_bounds__(256) void gemm_h(
    const __half* __restrict__ A, const __half* __restrict__ BT,
    const float* __restrict__ bias0, const float* __restrict__ bias1,
    const float* __restrict__ bias2,
    float* __restrict__ Cf,
    __half* __restrict__ H0, __half* __restrict__ H1, __half* __restrict__ H2)
{
    extern __shared__ __align__(16) char sm[];
    const uint32_t sb = smem_u32(sm);

    const int tid   = threadIdx.x;
    const int wid   = tid >> 5;
    const int lane  = tid & 31;
    const int wm    = wid >> 1;
    const int wn    = wid & 1;
    const int row0  = blockIdx.y * BM;
    const int col0g = blockIdx.x * BN;
    const int seg   = col0g >> 10;
    const int colL  = col0g & 1023;
    const float* bias = (seg == 0) ? bias0 : (seg == 1) ? bias1 : bias2;
    __half* Hout      = (seg == 0) ? H0    : (seg == 1) ? H1    : H2;

    wmma::fragment<wmma::accumulator, 16, 16, 16, float> acc[2][4];
#pragma unroll
    for (int i = 0; i < 2; i++)
#pragma unroll
        for (int j = 0; j < 4; j++) wmma::fill_fragment(acc[i][j], 0.f);

    // 128 rows x 64 halves per tile = 1024 16B-chunks; 4 per thread.
    auto load_stage = [&](int k0, int s) {
        const uint32_t abase = sb + s * STAGE_B;
        const uint32_t bbase = abase + TILE_H * 2;
#pragma unroll
        for (int i = 0; i < 4; i++) {
            const int idx = tid + i * 256;
            const int r = idx >> 3, c8 = (idx & 7) * 8;
            cp_async16(abase + (r * LDH + c8) * 2,
                       A + (size_t)(row0 + r) * GK + k0 + c8);
        }
#pragma unroll
        for (int i = 0; i < 4; i++) {
            const int idx = tid + i * 256;
            const int r = idx >> 3, c8 = (idx & 7) * 8;
            cp_async16(bbase + (r * LDH + c8) * 2,
                       BT + (size_t)(col0g + r) * GK + k0 + c8);
        }
        cp_commit();
    };

    load_stage(0, 0);

    const int NIT = GK / BKH;   // 16
    for (int it = 0; it < NIT; it++) {
        const int s = it & 1;
        if (it + 1 < NIT) { load_stage((it + 1) * BKH, s ^ 1); cp_wait<1>(); }
        else              { cp_wait<0>(); }
        __syncthreads();

        const __half* smA = (const __half*)(sm + s * STAGE_B);
        const __half* smB = smA + TILE_H;

#pragma unroll
        for (int kk = 0; kk < BKH; kk += 16) {
            wmma::fragment<wmma::matrix_a, 16, 16, 16, __half, wmma::row_major> af[2];
            wmma::fragment<wmma::matrix_b, 16, 16, 16, __half, wmma::col_major> bf[4];
#pragma unroll
            for (int i = 0; i < 2; i++)
                wmma::load_matrix_sync(af[i], smA + (wm * 32 + i * 16) * LDH + kk, LDH);
#pragma unroll
            for (int j = 0; j < 4; j++)
                wmma::load_matrix_sync(bf[j], smB + (wn * 64 + j * 16) * LDH + kk, LDH);
#pragma unroll
            for (int i = 0; i < 2; i++)
#pragma unroll
                for (int j = 0; j < 4; j++)
                    wmma::mma_sync(acc[i][j], af[i], bf[j], acc[i][j]);
        }
        __syncthreads();
    }

    float* Stg = (float*)sm + wid * 16 * 64;
    const int cb = wn * 64;
    const float bx = bias[colL + cb + lane * 2];
    const float by = bias[colL + cb + lane * 2 + 1];
#pragma unroll
    for (int i = 0; i < 2; i++) {
#pragma unroll
        for (int j = 0; j < 4; j++)
            wmma::store_matrix_sync(Stg + j * 16, acc[i][j], 64,
                                    wmma::mem_row_major);
        __syncwarp();
        const int rbase = row0 + wm * 32 + i * 16;
#pragma unroll
        for (int rr = 0; rr < 16; rr++) {
            float2 v = *(float2*)&Stg[rr * 64 + lane * 2];
            if (OH) {
                *(__half2*)&Hout[(size_t)(rbase + rr) * D_MODEL + colL + cb + lane * 2]
                    = __floats2half2_rn(v.x + bx, v.y + by);
            } else {
                float2 o; o.x = v.x + bx; o.y = v.y + by;
                *(float2*)&Cf[(size_t)(rbase + rr) * D_MODEL + colL + cb + lane * 2] = o;
            }
        }
        __syncwarp();
    }
}

// ---------------------------------------------------------------------------
// FA2-style causal attention. Q fragments pre-scaled by exact 0.125 (HMUL2,
// exponent-only, no rounding); exp arg fused: p = ex2(fma(s, L2E, -mn*L2E)).
// CTA = 128 Q rows, 8 warps x 16 rows. KV tiles of 64, cp.async double-buffer.
// ---------------------------------------------------------------------------
#define ALD 72
#define KVT_B (64 * ALD * 2)
#define AQ_OFF (4 * KVT_B)
#define ATT_SMEM (AQ_OFF + 128 * ALD * 2)   /* 55296 */
#define L2E 1.44269504f

__global__ __launch_bounds__(256, 2) void attn_mma(
    const __half* __restrict__ q, const __half* __restrict__ k,
    const __half* __restrict__ v, __half* __restrict__ o)
{
    extern __shared__ __align__(16) char sm[];
    const uint32_t sb = smem_u32(sm);

    const int tid  = threadIdx.x;
    const int lane = tid & 31;
    const int w    = tid >> 5;
    const int qt   = (gridDim.x - 1) - blockIdx.x;
    const int bh   = blockIdx.y;
    const int b    = bh >> 4;
    const int h    = bh & 15;
    const int qbase = qt * 128;

    const __half* qp = q + ((size_t)b * SEQ + qbase) * D_MODEL + h * HDIM;

#pragma unroll
    for (int i = 0; i < 4; i++) {
        const int idx = tid + i * 256;
        const int r = idx >> 3, c8 = (idx & 7) * 8;
        cp_async16(sb + AQ_OFF + (r * ALD + c8) * 2, qp + (size_t)r * D_MODEL + c8);
    }
    cp_commit();

    auto load_kv = [&](int kt, int s) {
        const size_t krow = (size_t)b * SEQ + kt * 64;
        const __half* kp = k + krow * D_MODEL + h * HDIM;
        const __half* vp = v + krow * D_MODEL + h * HDIM;
        const uint32_t kb = sb + s * 2 * KVT_B;
        const uint32_t vb = kb + KVT_B;
#pragma unroll
        for (int i = 0; i < 2; i++) {
            const int idx = tid + i * 256;
            const int r = idx >> 3, c8 = (idx & 7) * 8;
            cp_async16(kb + (r * ALD + c8) * 2, kp + (size_t)r * D_MODEL + c8);
            cp_async16(vb + (r * ALD + c8) * 2, vp + (size_t)r * D_MODEL + c8);
        }
        cp_commit();
    };
    load_kv(0, 0);

    const int lrow = ((lane >> 3) & 1) * 8 + (lane & 7);
    const int lcol = (lane >> 4) * 8;

    cp_wait<1>();
    __syncthreads();

    uint32_t qa[4][4];
#pragma unroll
    for (int kk = 0; kk < 4; kk++)
        ldsm4(qa[kk], sb + AQ_OFF +
              ((w * 16 + lrow) * ALD + kk * 16 + lcol) * 2);
    // Pre-scale Q by exact 0.125 (exponent shift in fp16; no rounding error).
    {
        const __half2 c8th = __float2half2_rn(0.125f);
#pragma unroll
        for (int kk = 0; kk < 4; kk++)
#pragma unroll
            for (int e = 0; e < 4; e++) {
                __half2 hv = *(__half2*)&qa[kk][e];
                hv = __hmul2(hv, c8th);
                qa[kk][e] = *(uint32_t*)&hv;
            }
    }

    float oacc[8][4];
#pragma unroll
    for (int j = 0; j < 8; j++)
#pragma unroll
        for (int e = 0; e < 4; e++) oacc[j][e] = 0.f;
    float m0 = -1e30f, m1 = -1e30f, l0 = 0.f, l1 = 0.f;

    const int wrow0 = qbase + w * 16;
    const int ntiles = 2 * qt + 2;

    for (int kt = 0; kt < ntiles; kt++) {
        const int s = kt & 1;
        cp_wait<0>();
        __syncthreads();
        if (kt + 1 < ntiles) load_kv(kt + 1, s ^ 1);

        if (kt * 64 <= wrow0 + 15) {
            const uint32_t kbb = sb + s * 2 * KVT_B;
            const uint32_t vbb = kbb + KVT_B;

            // ---- S = (Q/8) @ K^T ----
            float sacc[8][4];
#pragma unroll
            for (int j = 0; j < 8; j++)
#pragma unroll
                for (int e = 0; e < 4; e++) sacc[j][e] = 0.f;
#pragma unroll
            for (int kk = 0; kk < 4; kk++)
#pragma unroll
                for (int jj = 0; jj < 4; jj++) {
                    uint32_t kb4[4];
                    ldsm4(kb4, kbb + ((jj * 16 + lrow) * ALD + kk * 16 + lcol) * 2);
                    mma16816(sacc[2 * jj],     qa[kk], kb4[0], kb4[2]);
                    mma16816(sacc[2 * jj + 1], qa[kk], kb4[1], kb4[3]);
                }

            // ---- mask (raw S domain) ----
            if (kt * 64 + 63 > wrow0) {
                const int colb = kt * 64 + (lane & 3) * 2;
                const int r0g  = wrow0 + (lane >> 2);
#pragma unroll
                for (int j = 0; j < 8; j++) {
                    const int c = colb + j * 8;
                    if (c     > r0g)     sacc[j][0] = -1e30f;
                    if (c + 1 > r0g)     sacc[j][1] = -1e30f;
                    if (c     > r0g + 8) sacc[j][2] = -1e30f;
                    if (c + 1 > r0g + 8) sacc[j][3] = -1e30f;
                }
            }

            // ---- online softmax: max on raw S, exp via fused FFMA + MUFU ----
            float mx0 = sacc[0][0], mx1 = sacc[0][2];
#pragma unroll
            for (int j = 0; j < 8; j++) {
                mx0 = fmaxf(mx0, fmaxf(sacc[j][0], sacc[j][1]));
                mx1 = fmaxf(mx1, fmaxf(sacc[j][2], sacc[j][3]));
            }
            mx0 = fmaxf(mx0, __shfl_xor_sync(0xffffffffu, mx0, 1));
            mx0 = fmaxf(mx0, __shfl_xor_sync(0xffffffffu, mx0, 2));
            mx1 = fmaxf(mx1, __shfl_xor_sync(0xffffffffu, mx1, 1));
            mx1 = fmaxf(mx1, __shfl_xor_sync(0xffffffffu, mx1, 2));

            const float mn0 = fmaxf(m0, mx0);
            const float mn1 = fmaxf(m1, mx1);
            const float a0 = ex2((m0 - mn0) * L2E);
            const float a1 = ex2((m1 - mn1) * L2E);
            m0 = mn0; m1 = mn1;
            const float nm0 = -mn0 * L2E;
            const float nm1 = -mn1 * L2E;

            float s0 = 0.f, s1 = 0.f;
#pragma unroll
            for (int j = 0; j < 8; j++) {
                sacc[j][0] = ex2(fmaf(sacc[j][0], L2E, nm0));
                sacc[j][1] = ex2(fmaf(sacc[j][1], L2E, nm0));
                sacc[j][2] = ex2(fmaf(sacc[j][2], L2E, nm1));
                sacc[j][3] = ex2(fmaf(sacc[j][3], L2E, nm1));
                s0 += sacc[j][0] + sacc[j][1];
                s1 += sacc[j][2] + sacc[j][3];
            }
            s0 += __shfl_xor_sync(0xffffffffu, s0, 1);
            s0 += __shfl_xor_sync(0xffffffffu, s0, 2);
            s1 += __shfl_xor_sync(0xffffffffu, s1, 1);
            s1 += __shfl_xor_sync(0xffffffffu, s1, 2);
            l0 = l0 * a0 + s0;
            l1 = l1 * a1 + s1;

#pragma unroll
            for (int j = 0; j < 8; j++) {
                oacc[j][0] *= a0; oacc[j][1] *= a0;
                oacc[j][2] *= a1; oacc[j][3] *= a1;
            }

            // ---- O += P @ V ----
#pragma unroll
            for (int t = 0; t < 4; t++) {
                uint32_t pa[4];
                pa[0] = h2pack(sacc[2 * t][0],     sacc[2 * t][1]);
                pa[1] = h2pack(sacc[2 * t][2],     sacc[2 * t][3]);
                pa[2] = h2pack(sacc[2 * t + 1][0], sacc[2 * t + 1][1]);
                pa[3] = h2pack(sacc[2 * t + 1][2], sacc[2 * t + 1][3]);
#pragma unroll
                for (int jj = 0; jj < 4; jj++) {
                    uint32_t vb4[4];
                    ldsm4t(vb4, vbb + ((t * 16 + lrow) * ALD + jj * 16 + lcol) * 2);
                    mma16816(oacc[2 * jj],     pa, vb4[0], vb4[1]);
                    mma16816(oacc[2 * jj + 1], pa, vb4[2], vb4[3]);
                }
            }
        }
    }

    // ---- epilogue ----
    const float i0 = 1.f / l0;
    const float i1 = 1.f / l1;
    const int r0g = qbase + w * 16 + (lane >> 2);
    __half* o0 = o + ((size_t)b * SEQ + r0g) * D_MODEL + h * HDIM + (lane & 3) * 2;
    __half* o1 = o0 + 8 * D_MODEL;
#pragma unroll
    for (int j = 0; j < 8; j++) {
        *(__half2*)(o0 + j * 8) = __floats2half2_rn(oacc[j][0] * i0, oacc[j][1] * i0);
        *(__half2*)(o1 + j * 8) = __floats2half2_rn(oacc[j][2] * i1, oacc[j][3] * i1);
    }
}

// ---------------------------------------------------------------------------
extern "C" void kernel_launch(void* const* d_in, const int* in_sizes, int n_in,
                              void* d_out, int out_size)
{
    (void)in_sizes; (void)n_in; (void)out_size;
    const float* x  = (const float*)d_in[0];
    const float* Wq = (const float*)d_in[1];
    const float* bq = (const float*)d_in[2];
    const float* Wk = (const float*)d_in[3];
    const float* bk = (const float*)d_in[4];
    const float* Wv = (const float*)d_in[5];
    const float* bv = (const float*)d_in[6];
    const float* Wo = (const float*)d_in[7];
    const float* bo = (const float*)d_in[8];
    float* out = (float*)d_out;

    __half *gqh, *gkh, *gvh, *gxh, *goh, *gwth;
    cudaGetSymbolAddress((void**)&gqh, g_qh);
    cudaGetSymbolAddress((void**)&gkh, g_kh);
    cudaGetSymbolAddress((void**)&gvh, g_vh);
    cudaGetSymbolAddress((void**)&gxh, g_xh);
    cudaGetSymbolAddress((void**)&goh, g_oh);
    cudaGetSymbolAddress((void**)&gwth, g_wth);
    __half* wto = gwth + 3 * (size_t)D_MODEL * D_MODEL;

    const int NELEM = MROWS * D_MODEL;

    cudaFuncSetAttribute(attn_mma,
                         cudaFuncAttributeMaxDynamicSharedMemorySize, ATT_SMEM);
    cudaFuncSetAttribute(gemm_h<true>,
                         cudaFuncAttributeMaxDynamicSharedMemorySize, GEMM_SMEM);
    cudaFuncSetAttribute(gemm_h<false>,
                         cudaFuncAttributeMaxDynamicSharedMemorySize, GEMM_SMEM);

    dim3 gt(32, 32, 4);
    transpose_f2h4<<<gt, 256>>>(Wq, Wk, Wv, Wo, gwth);
    f2h<<<NELEM / (256 * 8), 256>>>(x, gxh, NELEM);

    dim3 gqkv(3 * D_MODEL / BN, MROWS / BM);   // (24, 64)
    gemm_h<true><<<gqkv, 256, GEMM_SMEM>>>(gxh, gwth, bq, bk, bv,
                                           nullptr, gqh, gkh, gvh);

    dim3 ga(SEQ / 128, BATCH * HEADS);         // (16, 64)
    attn_mma<<<ga, 256, ATT_SMEM>>>(gqh, gkh, gvh, goh);

    dim3 go(D_MODEL / BN, MROWS / BM);         // (8, 64)
    gemm_h<false><<<go, 256, GEMM_SMEM>>>(goh, wto, bo, nullptr, nullptr,
                                          out, nullptr, nullptr, nullptr);
}